// round 3
// baseline (speedup 1.0000x reference)
#include <cuda_runtime.h>
#include <cstdint>

// Problem constants
#define Bb 8
#define Tt 1024
#define Cc 1536
#define Hh 12
#define Dd 128
#define Ff 6144          // 4*C
#define BT 8192          // B*T
#define EPSF 1e-5f

// ---------------------------------------------------------------------------
// Scratch (static __device__ arrays; no runtime allocation)
// ---------------------------------------------------------------------------
__device__ float g_h [(size_t)BT * Cc];          // LN output (reused for LN2)
__device__ float g_q [(size_t)BT * Cc];          // (B,T,H*D)
__device__ float g_k [(size_t)BT * Cc];
__device__ float g_v [(size_t)BT * Cc];
__device__ float g_s [(size_t)Bb * Hh * Tt * Tt];// attention scores / probs
__device__ float g_o [(size_t)BT * Cc];          // attention output (B,T,C)
__device__ float g_x1[(size_t)BT * Cc];          // x + sa
__device__ float g_x2[(size_t)BT * Cc];          // after bn1
__device__ float g_f1[(size_t)BT * Ff];          // relu(h2@w1+b1)
__device__ float g_f2[(size_t)BT * Cc];          // x2 + ff

// ---------------------------------------------------------------------------
// Block reductions
// ---------------------------------------------------------------------------
__device__ __forceinline__ float blk_reduce_sum(float v) {
    __shared__ float sh[32];
    __syncthreads();
    int lane = threadIdx.x & 31, w = threadIdx.x >> 5;
    #pragma unroll
    for (int o = 16; o > 0; o >>= 1) v += __shfl_down_sync(0xffffffffu, v, o);
    if (lane == 0) sh[w] = v;
    __syncthreads();
    int nw = blockDim.x >> 5;
    if (w == 0) {
        v = (lane < nw) ? sh[lane] : 0.f;
        #pragma unroll
        for (int o = 16; o > 0; o >>= 1) v += __shfl_down_sync(0xffffffffu, v, o);
        if (lane == 0) sh[0] = v;
    }
    __syncthreads();
    return sh[0];
}

__device__ __forceinline__ float blk_reduce_max(float v) {
    __shared__ float sh[32];
    __syncthreads();
    int lane = threadIdx.x & 31, w = threadIdx.x >> 5;
    #pragma unroll
    for (int o = 16; o > 0; o >>= 1) v = fmaxf(v, __shfl_down_sync(0xffffffffu, v, o));
    if (lane == 0) sh[w] = v;
    __syncthreads();
    int nw = blockDim.x >> 5;
    if (w == 0) {
        v = (lane < nw) ? sh[lane] : -3.4e38f;
        #pragma unroll
        for (int o = 16; o > 0; o >>= 1) v = fmaxf(v, __shfl_down_sync(0xffffffffu, v, o));
        if (lane == 0) sh[0] = v;
    }
    __syncthreads();
    return sh[0];
}

// ---------------------------------------------------------------------------
// LayerNorm over last dim (C) — one block per row
// ---------------------------------------------------------------------------
__global__ void ln_kernel(const float* __restrict__ x, const float* __restrict__ g,
                          const float* __restrict__ b, float* __restrict__ out) {
    size_t row = blockIdx.x;
    const float* xr = x + row * Cc;
    float s = 0.f, s2 = 0.f;
    for (int i = threadIdx.x; i < Cc; i += blockDim.x) {
        float v = xr[i];
        s += v; s2 += v * v;
    }
    float S  = blk_reduce_sum(s);
    float S2 = blk_reduce_sum(s2);
    float mean = S * (1.0f / Cc);
    float var  = S2 * (1.0f / Cc) - mean * mean;
    float inv  = rsqrtf(var + EPSF);
    float* orow = out + row * Cc;
    for (int i = threadIdx.x; i < Cc; i += blockDim.x)
        orow[i] = (xr[i] - mean) * inv * g[i] + b[i];
}

// ---------------------------------------------------------------------------
// BatchNorm over (B, C) per T-channel — one block per t
// ---------------------------------------------------------------------------
__global__ void bn_kernel(const float* __restrict__ x, const float* __restrict__ g,
                          const float* __restrict__ bb, float* __restrict__ out) {
    int t = blockIdx.x;
    float s = 0.f, s2 = 0.f;
    for (int bi = 0; bi < Bb; bi++) {
        const float* xr = x + ((size_t)bi * Tt + t) * Cc;
        for (int c = threadIdx.x; c < Cc; c += blockDim.x) {
            float v = xr[c];
            s += v; s2 += v * v;
        }
    }
    const float cnt = (float)(Bb * Cc);
    float S  = blk_reduce_sum(s);
    float S2 = blk_reduce_sum(s2);
    float mean = S / cnt;
    float var  = S2 / cnt - mean * mean;
    float inv  = rsqrtf(var + EPSF);
    float gg = g[t], bv = bb[t];
    for (int bi = 0; bi < Bb; bi++) {
        const float* xr = x + ((size_t)bi * Tt + t) * Cc;
        float* orow = out + ((size_t)bi * Tt + t) * Cc;
        for (int c = threadIdx.x; c < Cc; c += blockDim.x)
            orow[c] = (xr[c] - mean) * inv * gg + bv;
    }
}

// ---------------------------------------------------------------------------
// Causal row softmax on the scores buffer — one block per (t, b*H+h)
// ---------------------------------------------------------------------------
__global__ void softmax_kernel(float* __restrict__ s) {
    int t = blockIdx.x;
    size_t z = blockIdx.y;
    float* row = s + (z * Tt + t) * (size_t)Tt;
    int n = t + 1;
    float mx = -3.4e38f;
    for (int i = threadIdx.x; i < n; i += blockDim.x) mx = fmaxf(mx, row[i]);
    mx = blk_reduce_max(mx);
    float se = 0.f;
    for (int i = threadIdx.x; i < n; i += blockDim.x) {
        float e = expf(row[i] - mx);
        row[i] = e;
        se += e;
    }
    se = blk_reduce_sum(se);
    float inv = 1.0f / se;
    for (int i = threadIdx.x; i < n; i += blockDim.x) row[i] *= inv;
    for (int i = n + threadIdx.x; i < Tt; i += blockDim.x) row[i] = 0.f;
}

// ---------------------------------------------------------------------------
// Generic tiled SGEMM: C = alpha*A*op(B) (+bias)(ReLU)(+add)
// Tile 128x128x16, 256 threads, 8x8 per thread.
// Requires M%128==0, N%128==0, K%16==0 (true for every call here).
// NT=1: B stored N-major (N x K row-major) -> computes A*B^T.
// Batch offsets: z -> zo=z/zdiv, zi=z%zdiv; ptr += zo*Outer + zi*Inner.
// ---------------------------------------------------------------------------
template <int NT>
__global__ __launch_bounds__(256, 2)
void sgemm_kernel(const float* __restrict__ A, const float* __restrict__ Bm,
                  float* __restrict__ C, int M, int N, int K,
                  int lda, int ldb, int ldc, float alpha,
                  const float* __restrict__ bias, const float* __restrict__ addp,
                  int doRelu, int zdiv,
                  long long aO, long long aI, long long bO, long long bI,
                  long long cO, long long cI) {
    long long z = blockIdx.z;
    long long zo = z / zdiv, zi = z % zdiv;
    A  += zo * aO + zi * aI;
    Bm += zo * bO + zi * bI;
    C  += zo * cO + zi * cI;
    if (addp) addp += zo * cO + zi * cI;

    __shared__ float As[16][128 + 4];
    __shared__ float Bs[16][128 + 4];

    int tid = threadIdx.x;
    int m0 = blockIdx.y * 128, n0 = blockIdx.x * 128;
    int tr = tid >> 4, tc = tid & 15;

    float acc[8][8];
    #pragma unroll
    for (int i = 0; i < 8; i++)
        #pragma unroll
        for (int j = 0; j < 8; j++) acc[i][j] = 0.f;

    int arow = tid >> 1, acol = (tid & 1) * 8;
    const float* aBase = A + (size_t)(m0 + arow) * lda + acol;

    for (int k0 = 0; k0 < K; k0 += 16) {
        // A tile: 128 rows x 16 k
        #pragma unroll
        for (int i = 0; i < 8; i++) As[acol + i][arow] = aBase[k0 + i];
        // B tile
        if (!NT) {
            int brow = tid >> 4, bcol = (tid & 15) * 8;
            const float* bp = Bm + (size_t)(k0 + brow) * ldb + n0 + bcol;
            #pragma unroll
            for (int i = 0; i < 8; i++) Bs[brow][bcol + i] = bp[i];
        } else {
            int brow = tid >> 1, bcol = (tid & 1) * 8;
            const float* bp = Bm + (size_t)(n0 + brow) * ldb + k0 + bcol;
            #pragma unroll
            for (int i = 0; i < 8; i++) Bs[bcol + i][brow] = bp[i];
        }
        __syncthreads();

        #pragma unroll
        for (int kk = 0; kk < 16; kk++) {
            float a[8], bv[8];
            #pragma unroll
            for (int i = 0; i < 8; i++) a[i] = As[kk][tr * 8 + i];
            #pragma unroll
            for (int j = 0; j < 8; j++) bv[j] = Bs[kk][tc * 8 + j];
            #pragma unroll
            for (int i = 0; i < 8; i++)
                #pragma unroll
                for (int j = 0; j < 8; j++) acc[i][j] = fmaf(a[i], bv[j], acc[i][j]);
        }
        __syncthreads();
    }

    #pragma unroll
    for (int i = 0; i < 8; i++) {
        int m = m0 + tr * 8 + i;
        float* cp = C + (size_t)m * ldc + n0 + tc * 8;
        const float* ap2 = addp ? addp + (size_t)m * ldc + n0 + tc * 8 : nullptr;
        #pragma unroll
        for (int j = 0; j < 8; j++) {
            float v = acc[i][j] * alpha;
            if (bias) v += bias[n0 + tc * 8 + j];
            if (doRelu) v = fmaxf(v, 0.f);
            if (ap2) v += ap2[j];
            cp[j] = v;
        }
    }
}

// ---------------------------------------------------------------------------
// Launch
// ---------------------------------------------------------------------------
extern "C" void kernel_launch(void* const* d_in, const int* in_sizes, int n_in,
                              void* d_out, int out_size) {
    const float* x     = (const float*)d_in[0];
    const float* wq    = (const float*)d_in[1];
    const float* wk    = (const float*)d_in[2];
    const float* wv    = (const float*)d_in[3];
    const float* wo    = (const float*)d_in[4];
    const float* bo    = (const float*)d_in[5];
    const float* ln1_g = (const float*)d_in[6];
    const float* ln1_b = (const float*)d_in[7];
    const float* ln2_g = (const float*)d_in[8];
    const float* ln2_b = (const float*)d_in[9];
    const float* w1    = (const float*)d_in[10];
    const float* b1    = (const float*)d_in[11];
    const float* w2    = (const float*)d_in[12];
    const float* b2    = (const float*)d_in[13];
    const float* bn1_g = (const float*)d_in[14];
    const float* bn1_b = (const float*)d_in[15];
    const float* bn2_g = (const float*)d_in[16];
    const float* bn2_b = (const float*)d_in[17];
    float* out = (float*)d_out;

    float* h  = nullptr; cudaGetSymbolAddress((void**)&h,  g_h);
    float* q  = nullptr; cudaGetSymbolAddress((void**)&q,  g_q);
    float* k  = nullptr; cudaGetSymbolAddress((void**)&k,  g_k);
    float* v  = nullptr; cudaGetSymbolAddress((void**)&v,  g_v);
    float* s  = nullptr; cudaGetSymbolAddress((void**)&s,  g_s);
    float* o  = nullptr; cudaGetSymbolAddress((void**)&o,  g_o);
    float* x1 = nullptr; cudaGetSymbolAddress((void**)&x1, g_x1);
    float* x2 = nullptr; cudaGetSymbolAddress((void**)&x2, g_x2);
    float* f1 = nullptr; cudaGetSymbolAddress((void**)&f1, g_f1);
    float* f2 = nullptr; cudaGetSymbolAddress((void**)&f2, g_f2);

    const long long CD = (long long)Cc * Dd;
    const long long TC = (long long)Tt * Cc;
    const long long TT = (long long)Tt * Tt;

    // 1. LN1
    ln_kernel<<<BT, 256>>>(x, ln1_g, ln1_b, h);

    // 2. QKV projections: per-head GEMM 8192x128x1536, output cols packed (B,T,H*D)
    {
        dim3 g(1, BT / 128, Hh);
        sgemm_kernel<0><<<g, 256>>>(h, wq, q, BT, Dd, Cc, Cc, Dd, Cc, 1.f,
                                    nullptr, nullptr, 0, 1 << 30,
                                    0, 0, 0, CD, 0, (long long)Dd);
        sgemm_kernel<0><<<g, 256>>>(h, wk, k, BT, Dd, Cc, Cc, Dd, Cc, 1.f,
                                    nullptr, nullptr, 0, 1 << 30,
                                    0, 0, 0, CD, 0, (long long)Dd);
        sgemm_kernel<0><<<g, 256>>>(h, wv, v, BT, Dd, Cc, Cc, Dd, Cc, 1.f,
                                    nullptr, nullptr, 0, 1 << 30,
                                    0, 0, 0, CD, 0, (long long)Dd);
    }

    // 3. Scores = alpha * Q K^T   (batched over b,h; z = b*H + h)
    {
        dim3 g(Tt / 128, Tt / 128, Bb * Hh);
        sgemm_kernel<1><<<g, 256>>>(q, k, s, Tt, Tt, Dd, Cc, Cc, Tt,
                                    0.08838834764831843f /* D^-0.5 */,
                                    nullptr, nullptr, 0, Hh,
                                    TC, (long long)Dd, TC, (long long)Dd,
                                    (long long)Hh * TT, TT);
    }

    // 4. Causal softmax
    softmax_kernel<<<dim3(Tt, Bb * Hh), 128>>>(s);

    // 5. O = P V  (batched)
    {
        dim3 g(1, Tt / 128, Bb * Hh);
        sgemm_kernel<0><<<g, 256>>>(s, v, o, Tt, Dd, Tt, Tt, Cc, Cc, 1.f,
                                    nullptr, nullptr, 0, Hh,
                                    (long long)Hh * TT, TT, TC, (long long)Dd,
                                    TC, (long long)Dd);
    }

    // 6. x1 = x + (O @ wo + bo)
    {
        dim3 g(Cc / 128, BT / 128, 1);
        sgemm_kernel<0><<<g, 256>>>(o, wo, x1, BT, Cc, Cc, Cc, Cc, Cc, 1.f,
                                    bo, x, 0, 1, 0, 0, 0, 0, 0, 0);
    }

    // 7. bn1
    bn_kernel<<<Tt, 256>>>(x1, bn1_g, bn1_b, x2);

    // 8. LN2
    ln_kernel<<<BT, 256>>>(x2, ln2_g, ln2_b, h);

    // 9. f1 = relu(h @ w1 + b1)
    {
        dim3 g(Ff / 128, BT / 128, 1);
        sgemm_kernel<0><<<g, 256>>>(h, w1, f1, BT, Ff, Cc, Cc, Ff, Ff, 1.f,
                                    b1, nullptr, 1, 1, 0, 0, 0, 0, 0, 0);
    }

    // 10. f2 = x2 + (f1 @ w2 + b2)
    {
        dim3 g(Cc / 128, BT / 128, 1);
        sgemm_kernel<0><<<g, 256>>>(f1, w2, f2, BT, Cc, Ff, Ff, Cc, Cc, 1.f,
                                    b2, x2, 0, 1, 0, 0, 0, 0, 0, 0);
    }

    // 11. bn2 -> out
    bn_kernel<<<Tt, 256>>>(f2, bn2_g, bn2_b, out);
}

// round 5
// speedup vs baseline: 2.5218x; 2.5218x over previous
#include <cuda_runtime.h>
#include <cstdint>

// Problem constants
#define Bb 8
#define Tt 1024
#define Cc 1536
#define Hh 12
#define Dd 128
#define Ff 6144          // 4*C
#define BT 8192          // B*T
#define EPSF 1e-5f

// ---------------------------------------------------------------------------
// Scratch (static __device__ arrays; no runtime allocation)
// ---------------------------------------------------------------------------
__device__ float g_h  [(size_t)BT * Cc];
__device__ float g_q  [(size_t)BT * Cc];
__device__ float g_k  [(size_t)BT * Cc];
__device__ float g_v  [(size_t)BT * Cc];
__device__ float g_s  [(size_t)Bb * Hh * Tt * Tt];
__device__ float g_o  [(size_t)BT * Cc];
__device__ float g_x1 [(size_t)BT * Cc];
__device__ float g_x2 [(size_t)BT * Cc];
__device__ float g_f1 [(size_t)BT * Ff];
__device__ float g_f2 [(size_t)BT * Cc];
// transposed operands (N x K, K-major)
__device__ float g_wqT[(size_t)Hh * Dd * Cc];
__device__ float g_wkT[(size_t)Hh * Dd * Cc];
__device__ float g_wvT[(size_t)Hh * Dd * Cc];
__device__ float g_woT[(size_t)Cc * Cc];
__device__ float g_w1T[(size_t)Ff * Cc];
__device__ float g_w2T[(size_t)Cc * Ff];
__device__ float g_vt [(size_t)Bb * Hh * Dd * Tt];

// ---------------------------------------------------------------------------
// tf32 helpers (baseline PTX, legal on plain compute_103)
// ---------------------------------------------------------------------------
__device__ __forceinline__ uint32_t f2tf(float f) {
    uint32_t u;
    asm("cvt.rna.tf32.f32 %0, %1;" : "=r"(u) : "f"(f));
    return u;
}

__device__ __forceinline__ void mma_tf32(float* c, const uint32_t* a, const uint32_t* b) {
    asm volatile(
        "mma.sync.aligned.m16n8k8.row.col.f32.tf32.tf32.f32 "
        "{%0,%1,%2,%3}, {%4,%5,%6,%7}, {%8,%9}, {%0,%1,%2,%3};"
        : "+f"(c[0]), "+f"(c[1]), "+f"(c[2]), "+f"(c[3])
        : "r"(a[0]), "r"(a[1]), "r"(a[2]), "r"(a[3]), "r"(b[0]), "r"(b[1]));
}

// ---------------------------------------------------------------------------
// tf32 tensor-core NT GEMM: C[M,N] = alpha * A[M,K] * B[N,K]^T (+bias)(ReLU)(+add)
// CTA tile 128x128, 8 warps (4M x 2N, warp tile 32x64), K chunk 16, double buf.
// causal: skip CTAs entirely above the diagonal (scores GEMM).
// kcap:   clamp K to m0+128 (PV GEMM — probs are zero beyond the diagonal).
// ---------------------------------------------------------------------------
#define PA 136   // A smem row stride (words): banks = m + 8*tig -> conflict-free
#define PB 20    // B smem row stride (words): banks = 20*gid + tig -> conflict-free

__global__ __launch_bounds__(256, 2)
void mma_gemm(const float* __restrict__ A, const float* __restrict__ Bm,
              float* __restrict__ C, int M, int N, int K,
              int lda, int ldb, int ldc, float alpha,
              const float* __restrict__ bias, const float* __restrict__ addp,
              int doRelu, int causal, int kcap, int zdiv,
              long long aO, long long aI, long long bO, long long bI,
              long long cO, long long cI) {
    int m0 = blockIdx.y * 128, n0 = blockIdx.x * 128;
    if (causal && n0 > m0 + 127) return;      // fully-masked tile
    if (kcap && K > m0 + 128) K = m0 + 128;   // PV: probs zero beyond diagonal

    long long z = blockIdx.z;
    long long zo = z / zdiv, zi = z % zdiv;
    A  += zo * aO + zi * aI;
    Bm += zo * bO + zi * bI;
    C  += zo * cO + zi * cI;
    if (addp) addp += zo * cO + zi * cI;

    __shared__ __align__(16) uint32_t As[2][16][PA];
    __shared__ __align__(16) uint32_t Bs[2][128][PB];

    int tid = threadIdx.x, wid = tid >> 5, lane = tid & 31;
    int gid = lane >> 2, tig = lane & 3;
    int wm = (wid & 3) * 32, wn = (wid >> 2) * 64;

    // gather/scatter assignments
    int am = tid & 127, akc = (tid >> 7) * 8;      // A: thread covers k akc..akc+7 of row am
    int bn = tid >> 1,  bkc = (tid & 1) * 8;       // B: thread covers k bkc..bkc+7 of row bn

    const float* aSrc = A + (size_t)(m0 + am) * lda + akc;
    const float* bSrc = Bm + (size_t)(n0 + bn) * ldb + bkc;

    float acc[2][8][4];
    #pragma unroll
    for (int i = 0; i < 2; i++)
        #pragma unroll
        for (int j = 0; j < 8; j++)
            #pragma unroll
            for (int r = 0; r < 4; r++) acc[i][j][r] = 0.f;

    int nch = K >> 4;

    float4 ra0, ra1, rb0, rb1;
    auto gather = [&](int k0) {
        ra0 = *(const float4*)(aSrc + k0);
        ra1 = *(const float4*)(aSrc + k0 + 4);
        rb0 = *(const float4*)(bSrc + k0);
        rb1 = *(const float4*)(bSrc + k0 + 4);
    };
    auto scatter = [&](int buf) {
        As[buf][akc + 0][am] = f2tf(ra0.x);
        As[buf][akc + 1][am] = f2tf(ra0.y);
        As[buf][akc + 2][am] = f2tf(ra0.z);
        As[buf][akc + 3][am] = f2tf(ra0.w);
        As[buf][akc + 4][am] = f2tf(ra1.x);
        As[buf][akc + 5][am] = f2tf(ra1.y);
        As[buf][akc + 6][am] = f2tf(ra1.z);
        As[buf][akc + 7][am] = f2tf(ra1.w);
        uint32_t* bp = &Bs[buf][bn][bkc];
        bp[0] = f2tf(rb0.x); bp[1] = f2tf(rb0.y);
        bp[2] = f2tf(rb0.z); bp[3] = f2tf(rb0.w);
        bp[4] = f2tf(rb1.x); bp[5] = f2tf(rb1.y);
        bp[6] = f2tf(rb1.z); bp[7] = f2tf(rb1.w);
    };

    gather(0);
    scatter(0);
    __syncthreads();

    for (int ch = 0; ch < nch; ch++) {
        int bsel = ch & 1;
        bool hasNext = (ch + 1 < nch);
        if (hasNext) gather((ch + 1) * 16);

        #pragma unroll
        for (int kk = 0; kk < 16; kk += 8) {
            uint32_t af[2][4];
            #pragma unroll
            for (int i = 0; i < 2; i++) {
                int mb = wm + i * 16 + gid;
                af[i][0] = As[bsel][kk + tig    ][mb];
                af[i][1] = As[bsel][kk + tig    ][mb + 8];
                af[i][2] = As[bsel][kk + tig + 4][mb];
                af[i][3] = As[bsel][kk + tig + 4][mb + 8];
            }
            uint32_t bf[8][2];
            #pragma unroll
            for (int j = 0; j < 8; j++) {
                const uint32_t* bp = &Bs[bsel][wn + j * 8 + gid][kk + tig];
                bf[j][0] = bp[0];
                bf[j][1] = bp[4];
            }
            #pragma unroll
            for (int i = 0; i < 2; i++)
                #pragma unroll
                for (int j = 0; j < 8; j++)
                    mma_tf32(acc[i][j], af[i], bf[j]);
        }

        if (hasNext) {
            scatter(bsel ^ 1);
            __syncthreads();
        }
    }

    // epilogue
    #pragma unroll
    for (int i = 0; i < 2; i++) {
        #pragma unroll
        for (int j = 0; j < 8; j++) {
            int r0 = m0 + wm + i * 16 + gid;
            int c  = n0 + wn + j * 8 + 2 * tig;
            #pragma unroll
            for (int h = 0; h < 2; h++) {
                int r = r0 + h * 8;
                float v0 = acc[i][j][2 * h + 0] * alpha;
                float v1 = acc[i][j][2 * h + 1] * alpha;
                if (bias) { v0 += bias[c]; v1 += bias[c + 1]; }
                if (doRelu) { v0 = fmaxf(v0, 0.f); v1 = fmaxf(v1, 0.f); }
                if (addp) {
                    const float* ap = addp + (size_t)r * ldc + c;
                    v0 += ap[0]; v1 += ap[1];
                }
                float2* cp = (float2*)(C + (size_t)r * ldc + c);
                *cp = make_float2(v0, v1);
            }
        }
    }
}

// ---------------------------------------------------------------------------
// Tiled transpose: out[c][r] = in[r][c]
// ---------------------------------------------------------------------------
__global__ void transpose_k(const float* __restrict__ in, float* __restrict__ out,
                            int R, int Cn, int ldi, int ldo, int zdiv,
                            long long iO, long long iI, long long oO, long long oI) {
    __shared__ float tile[32][33];
    long long z = blockIdx.z;
    in  += (z / zdiv) * iO + (z % zdiv) * iI;
    out += (z / zdiv) * oO + (z % zdiv) * oI;
    int r0 = blockIdx.y * 32, c0 = blockIdx.x * 32;
    int tx = threadIdx.x & 31, ty = threadIdx.x >> 5;
    #pragma unroll
    for (int i = ty; i < 32; i += 8)
        tile[i][tx] = in[(size_t)(r0 + i) * ldi + c0 + tx];
    __syncthreads();
    #pragma unroll
    for (int i = ty; i < 32; i += 8)
        out[(size_t)(c0 + i) * ldo + r0 + tx] = tile[tx][i];
}

// ---------------------------------------------------------------------------
// Block reductions
// ---------------------------------------------------------------------------
__device__ __forceinline__ float blk_reduce_sum(float v) {
    __shared__ float sh[32];
    __syncthreads();
    int lane = threadIdx.x & 31, w = threadIdx.x >> 5;
    #pragma unroll
    for (int o = 16; o > 0; o >>= 1) v += __shfl_down_sync(0xffffffffu, v, o);
    if (lane == 0) sh[w] = v;
    __syncthreads();
    int nw = blockDim.x >> 5;
    if (w == 0) {
        v = (lane < nw) ? sh[lane] : 0.f;
        #pragma unroll
        for (int o = 16; o > 0; o >>= 1) v += __shfl_down_sync(0xffffffffu, v, o);
        if (lane == 0) sh[0] = v;
    }
    __syncthreads();
    return sh[0];
}
__device__ __forceinline__ float blk_reduce_max(float v) {
    __shared__ float sh[32];
    __syncthreads();
    int lane = threadIdx.x & 31, w = threadIdx.x >> 5;
    #pragma unroll
    for (int o = 16; o > 0; o >>= 1) v = fmaxf(v, __shfl_down_sync(0xffffffffu, v, o));
    if (lane == 0) sh[w] = v;
    __syncthreads();
    int nw = blockDim.x >> 5;
    if (w == 0) {
        v = (lane < nw) ? sh[lane] : -3.4e38f;
        #pragma unroll
        for (int o = 16; o > 0; o >>= 1) v = fmaxf(v, __shfl_down_sync(0xffffffffu, v, o));
        if (lane == 0) sh[0] = v;
    }
    __syncthreads();
    return sh[0];
}

// ---------------------------------------------------------------------------
// LayerNorm / BatchNorm / Softmax
// ---------------------------------------------------------------------------
__global__ void ln_kernel(const float* __restrict__ x, const float* __restrict__ g,
                          const float* __restrict__ b, float* __restrict__ out) {
    size_t row = blockIdx.x;
    const float* xr = x + row * Cc;
    float s = 0.f, s2 = 0.f;
    for (int i = threadIdx.x; i < Cc; i += blockDim.x) {
        float v = xr[i]; s += v; s2 += v * v;
    }
    float S = blk_reduce_sum(s), S2 = blk_reduce_sum(s2);
    float mean = S * (1.0f / Cc);
    float var = S2 * (1.0f / Cc) - mean * mean;
    float inv = rsqrtf(var + EPSF);
    float* orow = out + row * Cc;
    for (int i = threadIdx.x; i < Cc; i += blockDim.x)
        orow[i] = (xr[i] - mean) * inv * g[i] + b[i];
}

__global__ void bn_kernel(const float* __restrict__ x, const float* __restrict__ g,
                          const float* __restrict__ bb, float* __restrict__ out) {
    int t = blockIdx.x;
    float s = 0.f, s2 = 0.f;
    for (int bi = 0; bi < Bb; bi++) {
        const float* xr = x + ((size_t)bi * Tt + t) * Cc;
        for (int c = threadIdx.x; c < Cc; c += blockDim.x) {
            float v = xr[c]; s += v; s2 += v * v;
        }
    }
    const float cnt = (float)(Bb * Cc);
    float S = blk_reduce_sum(s), S2 = blk_reduce_sum(s2);
    float mean = S / cnt;
    float var = S2 / cnt - mean * mean;
    float inv = rsqrtf(var + EPSF);
    float gg = g[t], bv = bb[t];
    for (int bi = 0; bi < Bb; bi++) {
        const float* xr = x + ((size_t)bi * Tt + t) * Cc;
        float* orow = out + ((size_t)bi * Tt + t) * Cc;
        for (int c = threadIdx.x; c < Cc; c += blockDim.x)
            orow[c] = (xr[c] - mean) * inv * gg + bv;
    }
}

__global__ void softmax_kernel(float* __restrict__ s) {
    int t = blockIdx.x;
    size_t z = blockIdx.y;
    float* row = s + (z * Tt + t) * (size_t)Tt;
    int n = t + 1;
    float mx = -3.4e38f;
    for (int i = threadIdx.x; i < n; i += blockDim.x) mx = fmaxf(mx, row[i]);
    mx = blk_reduce_max(mx);
    float se = 0.f;
    for (int i = threadIdx.x; i < n; i += blockDim.x) {
        float e = expf(row[i] - mx);
        row[i] = e;
        se += e;
    }
    se = blk_reduce_sum(se);
    float inv = 1.0f / se;
    for (int i = threadIdx.x; i < n; i += blockDim.x) row[i] *= inv;
    for (int i = n + threadIdx.x; i < Tt; i += blockDim.x) row[i] = 0.f;
}

// ---------------------------------------------------------------------------
// Launch
// ---------------------------------------------------------------------------
extern "C" void kernel_launch(void* const* d_in, const int* in_sizes, int n_in,
                              void* d_out, int out_size) {
    const float* x     = (const float*)d_in[0];
    const float* wq    = (const float*)d_in[1];
    const float* wk    = (const float*)d_in[2];
    const float* wv    = (const float*)d_in[3];
    const float* wo    = (const float*)d_in[4];
    const float* bo    = (const float*)d_in[5];
    const float* ln1_g = (const float*)d_in[6];
    const float* ln1_b = (const float*)d_in[7];
    const float* ln2_g = (const float*)d_in[8];
    const float* ln2_b = (const float*)d_in[9];
    const float* w1    = (const float*)d_in[10];
    const float* b1    = (const float*)d_in[11];
    const float* w2    = (const float*)d_in[12];
    const float* b2    = (const float*)d_in[13];
    const float* bn1_g = (const float*)d_in[14];
    const float* bn1_b = (const float*)d_in[15];
    const float* bn2_g = (const float*)d_in[16];
    const float* bn2_b = (const float*)d_in[17];
    float* out = (float*)d_out;

    float *h, *q, *k, *v, *s, *o, *x1, *x2, *f1, *f2;
    float *wqT, *wkT, *wvT, *woT, *w1T, *w2T, *vt;
    cudaGetSymbolAddress((void**)&h,  g_h);
    cudaGetSymbolAddress((void**)&q,  g_q);
    cudaGetSymbolAddress((void**)&k,  g_k);
    cudaGetSymbolAddress((void**)&v,  g_v);
    cudaGetSymbolAddress((void**)&s,  g_s);
    cudaGetSymbolAddress((void**)&o,  g_o);
    cudaGetSymbolAddress((void**)&x1, g_x1);
    cudaGetSymbolAddress((void**)&x2, g_x2);
    cudaGetSymbolAddress((void**)&f1, g_f1);
    cudaGetSymbolAddress((void**)&f2, g_f2);
    cudaGetSymbolAddress((void**)&wqT, g_wqT);
    cudaGetSymbolAddress((void**)&wkT, g_wkT);
    cudaGetSymbolAddress((void**)&wvT, g_wvT);
    cudaGetSymbolAddress((void**)&woT, g_woT);
    cudaGetSymbolAddress((void**)&w1T, g_w1T);
    cudaGetSymbolAddress((void**)&w2T, g_w2T);
    cudaGetSymbolAddress((void**)&vt,  g_vt);

    const long long CD = (long long)Cc * Dd;
    const long long TC = (long long)Tt * Cc;
    const long long TT = (long long)Tt * Tt;
    const long long DT = (long long)Dd * Tt;

    // --- weight transposes (N x K layout for NT GEMM) ---
    transpose_k<<<dim3(Dd / 32, Cc / 32, Hh), 256>>>(wq, wqT, Cc, Dd, Dd, Cc, 1, CD, 0, CD, 0);
    transpose_k<<<dim3(Dd / 32, Cc / 32, Hh), 256>>>(wk, wkT, Cc, Dd, Dd, Cc, 1, CD, 0, CD, 0);
    transpose_k<<<dim3(Dd / 32, Cc / 32, Hh), 256>>>(wv, wvT, Cc, Dd, Dd, Cc, 1, CD, 0, CD, 0);
    transpose_k<<<dim3(Cc / 32, Cc / 32, 1), 256>>>(wo, woT, Cc, Cc, Cc, Cc, 1, 0, 0, 0, 0);
    transpose_k<<<dim3(Ff / 32, Cc / 32, 1), 256>>>(w1, w1T, Cc, Ff, Ff, Cc, 1, 0, 0, 0, 0);
    transpose_k<<<dim3(Cc / 32, Ff / 32, 1), 256>>>(w2, w2T, Ff, Cc, Cc, Ff, 1, 0, 0, 0, 0);

    // 1. LN1
    ln_kernel<<<BT, 256>>>(x, ln1_g, ln1_b, h);

    // 2. QKV: per-head NT GEMM, M=8192, N=128, K=1536
    {
        dim3 g(1, BT / 128, Hh);
        mma_gemm<<<g, 256>>>(h, wqT, q, BT, Dd, Cc, Cc, Cc, Cc, 1.f,
                             nullptr, nullptr, 0, 0, 0, 1 << 30,
                             0, 0, 0, CD, 0, (long long)Dd);
        mma_gemm<<<g, 256>>>(h, wkT, k, BT, Dd, Cc, Cc, Cc, Cc, 1.f,
                             nullptr, nullptr, 0, 0, 0, 1 << 30,
                             0, 0, 0, CD, 0, (long long)Dd);
        mma_gemm<<<g, 256>>>(h, wvT, v, BT, Dd, Cc, Cc, Cc, Cc, 1.f,
                             nullptr, nullptr, 0, 0, 0, 1 << 30,
                             0, 0, 0, CD, 0, (long long)Dd);
    }

    // v -> vT (per b,h: [T,D] -> [D,T])
    transpose_k<<<dim3(Dd / 32, Tt / 32, Bb * Hh), 256>>>(
        v, vt, Tt, Dd, Cc, Tt, Hh, TC, (long long)Dd, (long long)Hh * DT, DT);

    // 3. scores = alpha * Q K^T   (z = b*H + h) — causal tile skip
    {
        dim3 g(Tt / 128, Tt / 128, Bb * Hh);
        mma_gemm<<<g, 256>>>(q, k, s, Tt, Tt, Dd, Cc, Cc, Tt,
                             0.08838834764831843f,
                             nullptr, nullptr, 0, 1, 0, Hh,
                             TC, (long long)Dd, TC, (long long)Dd,
                             (long long)Hh * TT, TT);
    }

    // 4. causal softmax
    softmax_kernel<<<dim3(Tt, Bb * Hh), 128>>>(s);

    // 5. O = P V  (B operand = vT, N=128, K capped at diagonal)
    {
        dim3 g(1, Tt / 128, Bb * Hh);
        mma_gemm<<<g, 256>>>(s, vt, o, Tt, Dd, Tt, Tt, Tt, Cc, 1.f,
                             nullptr, nullptr, 0, 0, 1, Hh,
                             (long long)Hh * TT, TT, (long long)Hh * DT, DT,
                             TC, (long long)Dd);
    }

    // 6. x1 = x + (O @ wo + bo)
    {
        dim3 g(Cc / 128, BT / 128, 1);
        mma_gemm<<<g, 256>>>(o, woT, x1, BT, Cc, Cc, Cc, Cc, Cc, 1.f,
                             bo, x, 0, 0, 0, 1, 0, 0, 0, 0, 0, 0);
    }

    // 7. bn1
    bn_kernel<<<Tt, 256>>>(x1, bn1_g, bn1_b, x2);

    // 8. LN2
    ln_kernel<<<BT, 256>>>(x2, ln2_g, ln2_b, h);

    // 9. f1 = relu(h @ w1 + b1)
    {
        dim3 g(Ff / 128, BT / 128, 1);
        mma_gemm<<<g, 256>>>(h, w1T, f1, BT, Ff, Cc, Cc, Cc, Ff, 1.f,
                             b1, nullptr, 1, 0, 0, 1, 0, 0, 0, 0, 0, 0);
    }

    // 10. f2 = x2 + (f1 @ w2 + b2)
    {
        dim3 g(Cc / 128, BT / 128, 1);
        mma_gemm<<<g, 256>>>(f1, w2T, f2, BT, Cc, Ff, Ff, Ff, Cc, 1.f,
                             b2, x2, 0, 0, 0, 1, 0, 0, 0, 0, 0, 0);
    }

    // 11. bn2 -> out
    bn_kernel<<<Tt, 256>>>(f2, bn2_g, bn2_b, out);
}

// round 7
// speedup vs baseline: 4.0507x; 1.6063x over previous
#include <cuda_runtime.h>
#include <cstdint>

// Problem constants
#define Bb 8
#define Tt 1024
#define Cc 1536
#define Hh 12
#define Dd 128
#define Ff 6144          // 4*C
#define BT 8192          // B*T
#define EPSF 1e-5f

// GEMM pipeline config
#define STAGES 4
#define STG_WORDS 5120      // per stage: A 128*20 + B 128*20 words
#define SMEM_BYTES (STAGES * STG_WORDS * 4)   // 81920

// ---------------------------------------------------------------------------
// Scratch (static __device__ arrays; no runtime allocation)
// ---------------------------------------------------------------------------
__device__ float g_h  [(size_t)BT * Cc];
__device__ float g_q  [(size_t)BT * Cc];
__device__ float g_k  [(size_t)BT * Cc];
__device__ float g_v  [(size_t)BT * Cc];
__device__ float g_s  [(size_t)Bb * Hh * Tt * Tt];
__device__ float g_o  [(size_t)BT * Cc];
__device__ float g_x1 [(size_t)BT * Cc];
__device__ float g_x2 [(size_t)BT * Cc];
__device__ float g_f1 [(size_t)BT * Ff];
__device__ float g_f2 [(size_t)BT * Cc];
// transposed operands (N x K, K-major)
__device__ float g_wqT[(size_t)Hh * Dd * Cc];
__device__ float g_wkT[(size_t)Hh * Dd * Cc];
__device__ float g_wvT[(size_t)Hh * Dd * Cc];
__device__ float g_woT[(size_t)Cc * Cc];
__device__ float g_w1T[(size_t)Ff * Cc];
__device__ float g_w2T[(size_t)Cc * Ff];
__device__ float g_vt [(size_t)Bb * Hh * Dd * Tt];

// ---------------------------------------------------------------------------
// Baseline-PTX helpers (legal on plain compute_103)
// ---------------------------------------------------------------------------
__device__ __forceinline__ uint32_t f2tf(float f) {
    uint32_t u;
    asm("cvt.rna.tf32.f32 %0, %1;" : "=r"(u) : "f"(f));
    return u;
}
__device__ __forceinline__ float roundtf(float f) {
    return __uint_as_float(f2tf(f));
}
__device__ __forceinline__ uint32_t smem_u32(const void* p) {
    uint32_t a;
    asm("{ .reg .u64 t; cvta.to.shared.u64 t, %1; cvt.u32.u64 %0, t; }" : "=r"(a) : "l"(p));
    return a;
}
__device__ __forceinline__ void cp16(uint32_t saddr, const void* gptr) {
    asm volatile("cp.async.cg.shared.global [%0], [%1], 16;" :: "r"(saddr), "l"(gptr));
}
#define CP_COMMIT() asm volatile("cp.async.commit_group;" ::: "memory")
#define CP_WAIT(n)  asm volatile("cp.async.wait_group %0;" :: "n"(n) : "memory")

__device__ __forceinline__ void mma_tf32(float* c, const uint32_t* a, const uint32_t* b) {
    asm volatile(
        "mma.sync.aligned.m16n8k8.row.col.f32.tf32.tf32.f32 "
        "{%0,%1,%2,%3}, {%4,%5,%6,%7}, {%8,%9}, {%0,%1,%2,%3};"
        : "+f"(c[0]), "+f"(c[1]), "+f"(c[2]), "+f"(c[3])
        : "r"(a[0]), "r"(a[1]), "r"(a[2]), "r"(a[3]), "r"(b[0]), "r"(b[1]));
}

// ---------------------------------------------------------------------------
// tf32 tensor-core NT GEMM: C[M,N] = alpha * A[M,K] * B[N,K]^T (+bias)(ReLU)(+add)
// CTA tile 128x128, 8 warps (4M x 2N, warp 32x64), K chunk 16, 4-stage cp.async.
// Operands MUST already be tf32-rounded (producers round).
// Smem per stage: A[m][k] stride 20 words, B[n][k] stride 20 words (conflict-free).
// ---------------------------------------------------------------------------
__global__ __launch_bounds__(256, 2)
void mma_gemm(const float* __restrict__ A, const float* __restrict__ Bm,
              float* __restrict__ C, int M, int N, int K,
              int lda, int ldb, int ldc, float alpha,
              const float* __restrict__ bias, const float* __restrict__ addp,
              int doRelu, int roundOut, int causal, int kcap, int zdiv,
              long long aO, long long aI, long long bO, long long bI,
              long long cO, long long cI) {
    int m0 = blockIdx.y * 128, n0 = blockIdx.x * 128;
    if (causal && n0 > m0 + 127) return;      // fully-masked tile
    if (kcap && K > m0 + 128) K = m0 + 128;   // PV: probs zero beyond diagonal

    long long z = blockIdx.z;
    long long zo = z / zdiv, zi = z % zdiv;
    A  += zo * aO + zi * aI;
    Bm += zo * bO + zi * bI;
    C  += zo * cO + zi * cI;
    if (addp) addp += zo * cO + zi * cI;

    extern __shared__ uint32_t sm[];
    uint32_t sbase = smem_u32(sm);

    int tid = threadIdx.x, wid = tid >> 5, lane = tid & 31;
    int gid = lane >> 2, tig = lane & 3;
    int wm = (wid & 3) * 32, wn = (wid >> 2) * 64;

    // cp.async mapping: thread -> rows {lrow, lrow+64}, 16B quad lq
    int lrow = tid >> 2, lq = (tid & 3) * 4;
    const float* aR0 = A + (size_t)(m0 + lrow) * lda + lq;
    const float* aR1 = aR0 + (size_t)64 * lda;
    const float* bR0 = Bm + (size_t)(n0 + lrow) * ldb + lq;
    const float* bR1 = bR0 + (size_t)64 * ldb;
    uint32_t dstA = sbase + (uint32_t)(lrow * 20 + lq) * 4;
    uint32_t dstB = dstA + 2560u * 4;

    int nch = K >> 4;

    auto issue = [&](int ch) {
        if (ch < nch) {
            uint32_t so = (uint32_t)(ch & (STAGES - 1)) * (STG_WORDS * 4);
            int k0 = ch * 16;
            cp16(dstA + so,             aR0 + k0);
            cp16(dstA + so + 64 * 80,   aR1 + k0);
            cp16(dstB + so,             bR0 + k0);
            cp16(dstB + so + 64 * 80,   bR1 + k0);
        }
        CP_COMMIT();
    };

    float acc[2][8][4];
    #pragma unroll
    for (int i = 0; i < 2; i++)
        #pragma unroll
        for (int j = 0; j < 8; j++)
            #pragma unroll
            for (int r = 0; r < 4; r++) acc[i][j][r] = 0.f;

    issue(0); issue(1); issue(2);

    for (int ch = 0; ch < nch; ch++) {
        CP_WAIT(STAGES - 2);
        __syncthreads();
        issue(ch + STAGES - 1);

        const uint32_t* As = sm + (ch & (STAGES - 1)) * STG_WORDS;
        const uint32_t* Bs = As + 2560;

        #pragma unroll
        for (int kk = 0; kk < 16; kk += 8) {
            uint32_t af[2][4];
            #pragma unroll
            for (int i = 0; i < 2; i++) {
                int mb = wm + i * 16 + gid;
                af[i][0] = As[mb * 20 + kk + tig];
                af[i][1] = As[(mb + 8) * 20 + kk + tig];
                af[i][2] = As[mb * 20 + kk + tig + 4];
                af[i][3] = As[(mb + 8) * 20 + kk + tig + 4];
            }
            uint32_t bf[8][2];
            #pragma unroll
            for (int j = 0; j < 8; j++) {
                const uint32_t* bp = &Bs[(wn + j * 8 + gid) * 20 + kk + tig];
                bf[j][0] = bp[0];
                bf[j][1] = bp[4];
            }
            #pragma unroll
            for (int i = 0; i < 2; i++)
                #pragma unroll
                for (int j = 0; j < 8; j++)
                    mma_tf32(acc[i][j], af[i], bf[j]);
        }
    }

    // epilogue
    #pragma unroll
    for (int i = 0; i < 2; i++) {
        #pragma unroll
        for (int j = 0; j < 8; j++) {
            int r0 = m0 + wm + i * 16 + gid;
            int c  = n0 + wn + j * 8 + 2 * tig;
            #pragma unroll
            for (int h = 0; h < 2; h++) {
                int r = r0 + h * 8;
                float v0 = acc[i][j][2 * h + 0] * alpha;
                float v1 = acc[i][j][2 * h + 1] * alpha;
                if (bias) { v0 += bias[c]; v1 += bias[c + 1]; }
                if (doRelu) { v0 = fmaxf(v0, 0.f); v1 = fmaxf(v1, 0.f); }
                if (addp) {
                    const float* ap = addp + (size_t)r * ldc + c;
                    v0 += ap[0]; v1 += ap[1];
                }
                if (roundOut) { v0 = roundtf(v0); v1 = roundtf(v1); }
                float2* cp = (float2*)(C + (size_t)r * ldc + c);
                *cp = make_float2(v0, v1);
            }
        }
    }
}

// ---------------------------------------------------------------------------
// Tiled transpose: out[c][r] = tf32round(in[r][c])
// ---------------------------------------------------------------------------
__global__ void transpose_k(const float* __restrict__ in, float* __restrict__ out,
                            int R, int Cn, int ldi, int ldo, int zdiv,
                            long long iO, long long iI, long long oO, long long oI) {
    __shared__ float tile[32][33];
    long long z = blockIdx.z;
    in  += (z / zdiv) * iO + (z % zdiv) * iI;
    out += (z / zdiv) * oO + (z % zdiv) * oI;
    int r0 = blockIdx.y * 32, c0 = blockIdx.x * 32;
    int tx = threadIdx.x & 31, ty = threadIdx.x >> 5;
    #pragma unroll
    for (int i = ty; i < 32; i += 8)
        tile[i][tx] = in[(size_t)(r0 + i) * ldi + c0 + tx];
    __syncthreads();
    #pragma unroll
    for (int i = ty; i < 32; i += 8)
        out[(size_t)(c0 + i) * ldo + r0 + tx] = roundtf(tile[tx][i]);
}

// ---------------------------------------------------------------------------
// Block reductions
// ---------------------------------------------------------------------------
__device__ __forceinline__ float blk_reduce_sum(float v) {
    __shared__ float sh[32];
    __syncthreads();
    int lane = threadIdx.x & 31, w = threadIdx.x >> 5;
    #pragma unroll
    for (int o = 16; o > 0; o >>= 1) v += __shfl_down_sync(0xffffffffu, v, o);
    if (lane == 0) sh[w] = v;
    __syncthreads();
    int nw = blockDim.x >> 5;
    if (w == 0) {
        v = (lane < nw) ? sh[lane] : 0.f;
        #pragma unroll
        for (int o = 16; o > 0; o >>= 1) v += __shfl_down_sync(0xffffffffu, v, o);
        if (lane == 0) sh[0] = v;
    }
    __syncthreads();
    return sh[0];
}
__device__ __forceinline__ float blk_reduce_max(float v) {
    __shared__ float sh[32];
    __syncthreads();
    int lane = threadIdx.x & 31, w = threadIdx.x >> 5;
    #pragma unroll
    for (int o = 16; o > 0; o >>= 1) v = fmaxf(v, __shfl_down_sync(0xffffffffu, v, o));
    if (lane == 0) sh[w] = v;
    __syncthreads();
    int nw = blockDim.x >> 5;
    if (w == 0) {
        v = (lane < nw) ? sh[lane] : -3.4e38f;
        #pragma unroll
        for (int o = 16; o > 0; o >>= 1) v = fmaxf(v, __shfl_down_sync(0xffffffffu, v, o));
        if (lane == 0) sh[0] = v;
    }
    __syncthreads();
    return sh[0];
}

// ---------------------------------------------------------------------------
// LayerNorm (output tf32-rounded: feeds GEMMs only)
// ---------------------------------------------------------------------------
__global__ void ln_kernel(const float* __restrict__ x, const float* __restrict__ g,
                          const float* __restrict__ b, float* __restrict__ out) {
    size_t row = blockIdx.x;
    const float* xr = x + row * Cc;
    float s = 0.f, s2 = 0.f;
    for (int i = threadIdx.x; i < Cc; i += blockDim.x) {
        float v = xr[i]; s += v; s2 += v * v;
    }
    float S = blk_reduce_sum(s), S2 = blk_reduce_sum(s2);
    float mean = S * (1.0f / Cc);
    float var = S2 * (1.0f / Cc) - mean * mean;
    float inv = rsqrtf(var + EPSF);
    float* orow = out + row * Cc;
    for (int i = threadIdx.x; i < Cc; i += blockDim.x)
        orow[i] = roundtf((xr[i] - mean) * inv * g[i] + b[i]);
}

// ---------------------------------------------------------------------------
// BatchNorm over (B, C) per T-channel (NOT rounded: feeds residual path)
// ---------------------------------------------------------------------------
__global__ void bn_kernel(const float* __restrict__ x, const float* __restrict__ g,
                          const float* __restrict__ bb, float* __restrict__ out) {
    int t = blockIdx.x;
    float s = 0.f, s2 = 0.f;
    for (int bi = 0; bi < Bb; bi++) {
        const float* xr = x + ((size_t)bi * Tt + t) * Cc;
        for (int c = threadIdx.x; c < Cc; c += blockDim.x) {
            float v = xr[c]; s += v; s2 += v * v;
        }
    }
    const float cnt = (float)(Bb * Cc);
    float S = blk_reduce_sum(s), S2 = blk_reduce_sum(s2);
    float mean = S / cnt;
    float var = S2 / cnt - mean * mean;
    float inv = rsqrtf(var + EPSF);
    float gg = g[t], bv = bb[t];
    for (int bi = 0; bi < Bb; bi++) {
        const float* xr = x + ((size_t)bi * Tt + t) * Cc;
        float* orow = out + ((size_t)bi * Tt + t) * Cc;
        for (int c = threadIdx.x; c < Cc; c += blockDim.x)
            orow[c] = (xr[c] - mean) * inv * gg + bv;
    }
}

// ---------------------------------------------------------------------------
// Causal row softmax (probs tf32-rounded: feed PV GEMM)
// ---------------------------------------------------------------------------
__global__ void softmax_kernel(float* __restrict__ s) {
    int t = blockIdx.x;
    size_t z = blockIdx.y;
    float* row = s + (z * Tt + t) * (size_t)Tt;
    int n = t + 1;
    float mx = -3.4e38f;
    for (int i = threadIdx.x; i < n; i += blockDim.x) mx = fmaxf(mx, row[i]);
    mx = blk_reduce_max(mx);
    float se = 0.f;
    for (int i = threadIdx.x; i < n; i += blockDim.x) {
        float e = expf(row[i] - mx);
        row[i] = e;
        se += e;
    }
    se = blk_reduce_sum(se);
    float inv = 1.0f / se;
    for (int i = threadIdx.x; i < n; i += blockDim.x) row[i] = roundtf(row[i] * inv);
    for (int i = n + threadIdx.x; i < Tt; i += blockDim.x) row[i] = 0.f;
}

// ---------------------------------------------------------------------------
// Launch
// ---------------------------------------------------------------------------
extern "C" void kernel_launch(void* const* d_in, const int* in_sizes, int n_in,
                              void* d_out, int out_size) {
    const float* x     = (const float*)d_in[0];
    const float* wq    = (const float*)d_in[1];
    const float* wk    = (const float*)d_in[2];
    const float* wv    = (const float*)d_in[3];
    const float* wo    = (const float*)d_in[4];
    const float* bo    = (const float*)d_in[5];
    const float* ln1_g = (const float*)d_in[6];
    const float* ln1_b = (const float*)d_in[7];
    const float* ln2_g = (const float*)d_in[8];
    const float* ln2_b = (const float*)d_in[9];
    const float* w1    = (const float*)d_in[10];
    const float* b1    = (const float*)d_in[11];
    const float* w2    = (const float*)d_in[12];
    const float* b2    = (const float*)d_in[13];
    const float* bn1_g = (const float*)d_in[14];
    const float* bn1_b = (const float*)d_in[15];
    const float* bn2_g = (const float*)d_in[16];
    const float* bn2_b = (const float*)d_in[17];
    float* out = (float*)d_out;

    float *h, *q, *k, *v, *s, *o, *x1, *x2, *f1, *f2;
    float *wqT, *wkT, *wvT, *woT, *w1T, *w2T, *vt;
    cudaGetSymbolAddress((void**)&h,  g_h);
    cudaGetSymbolAddress((void**)&q,  g_q);
    cudaGetSymbolAddress((void**)&k,  g_k);
    cudaGetSymbolAddress((void**)&v,  g_v);
    cudaGetSymbolAddress((void**)&s,  g_s);
    cudaGetSymbolAddress((void**)&o,  g_o);
    cudaGetSymbolAddress((void**)&x1, g_x1);
    cudaGetSymbolAddress((void**)&x2, g_x2);
    cudaGetSymbolAddress((void**)&f1, g_f1);
    cudaGetSymbolAddress((void**)&f2, g_f2);
    cudaGetSymbolAddress((void**)&wqT, g_wqT);
    cudaGetSymbolAddress((void**)&wkT, g_wkT);
    cudaGetSymbolAddress((void**)&wvT, g_wvT);
    cudaGetSymbolAddress((void**)&woT, g_woT);
    cudaGetSymbolAddress((void**)&w1T, g_w1T);
    cudaGetSymbolAddress((void**)&w2T, g_w2T);
    cudaGetSymbolAddress((void**)&vt,  g_vt);

    cudaFuncSetAttribute(mma_gemm, cudaFuncAttributeMaxDynamicSharedMemorySize, SMEM_BYTES);

    const long long CD = (long long)Cc * Dd;
    const long long TC = (long long)Tt * Cc;
    const long long TT = (long long)Tt * Tt;
    const long long DT = (long long)Dd * Tt;

    // --- weight transposes (N x K layout, tf32-rounded) ---
    transpose_k<<<dim3(Dd / 32, Cc / 32, Hh), 256>>>(wq, wqT, Cc, Dd, Dd, Cc, 1, CD, 0, CD, 0);
    transpose_k<<<dim3(Dd / 32, Cc / 32, Hh), 256>>>(wk, wkT, Cc, Dd, Dd, Cc, 1, CD, 0, CD, 0);
    transpose_k<<<dim3(Dd / 32, Cc / 32, Hh), 256>>>(wv, wvT, Cc, Dd, Dd, Cc, 1, CD, 0, CD, 0);
    transpose_k<<<dim3(Cc / 32, Cc / 32, 1), 256>>>(wo, woT, Cc, Cc, Cc, Cc, 1, 0, 0, 0, 0);
    transpose_k<<<dim3(Ff / 32, Cc / 32, 1), 256>>>(w1, w1T, Cc, Ff, Ff, Cc, 1, 0, 0, 0, 0);
    transpose_k<<<dim3(Cc / 32, Ff / 32, 1), 256>>>(w2, w2T, Ff, Cc, Cc, Ff, 1, 0, 0, 0, 0);

    // 1. LN1 (rounded)
    ln_kernel<<<BT, 256>>>(x, ln1_g, ln1_b, h);

    // 2. QKV: per-head NT GEMM, M=8192, N=128, K=1536 (outputs rounded)
    {
        dim3 g(1, BT / 128, Hh);
        mma_gemm<<<g, 256, SMEM_BYTES>>>(h, wqT, q, BT, Dd, Cc, Cc, Cc, Cc, 1.f,
                             nullptr, nullptr, 0, 1, 0, 0, 1 << 30,
                             0, 0, 0, CD, 0, (long long)Dd);
        mma_gemm<<<g, 256, SMEM_BYTES>>>(h, wkT, k, BT, Dd, Cc, Cc, Cc, Cc, 1.f,
                             nullptr, nullptr, 0, 1, 0, 0, 1 << 30,
                             0, 0, 0, CD, 0, (long long)Dd);
        mma_gemm<<<g, 256, SMEM_BYTES>>>(h, wvT, v, BT, Dd, Cc, Cc, Cc, Cc, 1.f,
                             nullptr, nullptr, 0, 1, 0, 0, 1 << 30,
                             0, 0, 0, CD, 0, (long long)Dd);
    }

    // v -> vT (per b,h: [T,D] -> [D,T], rounded)
    transpose_k<<<dim3(Dd / 32, Tt / 32, Bb * Hh), 256>>>(
        v, vt, Tt, Dd, Cc, Tt, Hh, TC, (long long)Dd, (long long)Hh * DT, DT);

    // 3. scores = alpha * Q K^T — causal tile skip
    {
        dim3 g(Tt / 128, Tt / 128, Bb * Hh);
        mma_gemm<<<g, 256, SMEM_BYTES>>>(q, k, s, Tt, Tt, Dd, Cc, Cc, Tt,
                             0.08838834764831843f,
                             nullptr, nullptr, 0, 0, 1, 0, Hh,
                             TC, (long long)Dd, TC, (long long)Dd,
                             (long long)Hh * TT, TT);
    }

    // 4. causal softmax (probs rounded)
    softmax_kernel<<<dim3(Tt, Bb * Hh), 128>>>(s);

    // 5. O = P V (K capped at diagonal; output rounded)
    {
        dim3 g(1, Tt / 128, Bb * Hh);
        mma_gemm<<<g, 256, SMEM_BYTES>>>(s, vt, o, Tt, Dd, Tt, Tt, Tt, Cc, 1.f,
                             nullptr, nullptr, 0, 1, 0, 1, Hh,
                             (long long)Hh * TT, TT, (long long)Hh * DT, DT,
                             TC, (long long)Dd);
    }

    // 6. x1 = x + (O @ wo + bo)
    {
        dim3 g(Cc / 128, BT / 128, 1);
        mma_gemm<<<g, 256, SMEM_BYTES>>>(o, woT, x1, BT, Cc, Cc, Cc, Cc, Cc, 1.f,
                             bo, x, 0, 0, 0, 0, 1, 0, 0, 0, 0, 0, 0);
    }

    // 7. bn1
    bn_kernel<<<Tt, 256>>>(x1, bn1_g, bn1_b, x2);

    // 8. LN2 (rounded)
    ln_kernel<<<BT, 256>>>(x2, ln2_g, ln2_b, h);

    // 9. f1 = relu(h @ w1 + b1) (rounded)
    {
        dim3 g(Ff / 128, BT / 128, 1);
        mma_gemm<<<g, 256, SMEM_BYTES>>>(h, w1T, f1, BT, Ff, Cc, Cc, Cc, Ff, 1.f,
                             b1, nullptr, 1, 1, 0, 0, 1, 0, 0, 0, 0, 0, 0);
    }

    // 10. f2 = x2 + (f1 @ w2 + b2)
    {
        dim3 g(Cc / 128, BT / 128, 1);
        mma_gemm<<<g, 256, SMEM_BYTES>>>(f1, w2T, f2, BT, Cc, Ff, Ff, Ff, Cc, 1.f,
                             b2, x2, 0, 0, 0, 0, 1, 0, 0, 0, 0, 0, 0);
    }

    // 11. bn2 -> out
    bn_kernel<<<Tt, 256>>>(f2, bn2_g, bn2_b, out);
}

// round 8
// speedup vs baseline: 7.8277x; 1.9324x over previous
#include <cuda_runtime.h>
#include <cuda_fp16.h>
#include <cstdint>

// Problem constants
#define Bb 8
#define Tt 1024
#define Cc 1536
#define Hh 12
#define Dd 128
#define Ff 6144          // 4*C
#define BT 8192          // B*T
#define EPSF 1e-5f

// GEMM pipeline config: 4 stages, K-chunk 32 (fp16)
// per stage: A 128 rows x 80B + B 128 rows x 80B = 20480 B
#define STG_BYTES 20480
#define SMEM_BYTES (4 * STG_BYTES)   // 81920

// ---------------------------------------------------------------------------
// Scratch (static __device__ arrays; no runtime allocation)
// ---------------------------------------------------------------------------
__device__ __align__(256) __half g_h  [(size_t)BT * Cc];
__device__ __align__(256) __half g_q  [(size_t)BT * Cc];
__device__ __align__(256) __half g_k  [(size_t)BT * Cc];
__device__ __align__(256) __half g_v  [(size_t)BT * Cc];
__device__ __align__(256) __half g_s  [(size_t)Bb * Hh * Tt * Tt];
__device__ __align__(256) __half g_o  [(size_t)BT * Cc];
__device__ __align__(256) __half g_f1 [(size_t)BT * Ff];
__device__ __align__(256) __half g_wqT[(size_t)Hh * Dd * Cc];
__device__ __align__(256) __half g_wkT[(size_t)Hh * Dd * Cc];
__device__ __align__(256) __half g_wvT[(size_t)Hh * Dd * Cc];
__device__ __align__(256) __half g_woT[(size_t)Cc * Cc];
__device__ __align__(256) __half g_w1T[(size_t)Ff * Cc];
__device__ __align__(256) __half g_w2T[(size_t)Cc * Ff];
__device__ __align__(256) __half g_vt [(size_t)Bb * Hh * Dd * Tt];
// fp32 residual-path tensors
__device__ float g_x1 [(size_t)BT * Cc];
__device__ float g_x2 [(size_t)BT * Cc];
__device__ float g_f2 [(size_t)BT * Cc];

// ---------------------------------------------------------------------------
// Baseline-PTX helpers (legal on plain compute_103)
// ---------------------------------------------------------------------------
__device__ __forceinline__ uint32_t smem_u32(const void* p) {
    uint32_t a;
    asm("{ .reg .u64 t; cvta.to.shared.u64 t, %1; cvt.u32.u64 %0, t; }" : "=r"(a) : "l"(p));
    return a;
}
__device__ __forceinline__ void cp16(uint32_t saddr, const void* gptr) {
    asm volatile("cp.async.cg.shared.global [%0], [%1], 16;" :: "r"(saddr), "l"(gptr));
}
#define CP_COMMIT() asm volatile("cp.async.commit_group;" ::: "memory")
#define CP_WAIT(n)  asm volatile("cp.async.wait_group %0;" :: "n"(n) : "memory")

__device__ __forceinline__ void ldsm4(uint32_t& r0, uint32_t& r1, uint32_t& r2,
                                      uint32_t& r3, uint32_t addr) {
    asm volatile("ldmatrix.sync.aligned.m8n8.x4.shared.b16 {%0,%1,%2,%3}, [%4];"
                 : "=r"(r0), "=r"(r1), "=r"(r2), "=r"(r3) : "r"(addr));
}
__device__ __forceinline__ void mma_f16(float* c, const uint32_t* a, const uint32_t* b) {
    asm volatile(
        "mma.sync.aligned.m16n8k16.row.col.f32.f16.f16.f32 "
        "{%0,%1,%2,%3}, {%4,%5,%6,%7}, {%8,%9}, {%0,%1,%2,%3};"
        : "+f"(c[0]), "+f"(c[1]), "+f"(c[2]), "+f"(c[3])
        : "r"(a[0]), "r"(a[1]), "r"(a[2]), "r"(a[3]), "r"(b[0]), "r"(b[1]));
}

// ---------------------------------------------------------------------------
// fp16 tensor-core NT GEMM: C[M,N] = alpha * A[M,K] * B[N,K]^T (+bias)(ReLU)(+add)
// CTA tile 128x128, 8 warps (4M x 2N, warp 32x64), K chunk 32, 4-stage cp.async.
// Smem rows: 32 halves (64B) padded to 80B stride -> ldmatrix conflict-free.
// outHalf: store __half2 (rounded); else float2. addp/bias always fp32.
// ---------------------------------------------------------------------------
__global__ __launch_bounds__(256, 2)
void hgemm(const __half* __restrict__ A, const __half* __restrict__ Bm,
           void* __restrict__ Cv, int M, int N, int K,
           int lda, int ldb, int ldc, float alpha,
           const float* __restrict__ bias, const float* __restrict__ addp,
           int doRelu, int outHalf, int causal, int kcap, int zdiv,
           long long aO, long long aI, long long bO, long long bI,
           long long cO, long long cI) {
    int m0 = blockIdx.y * 128, n0 = blockIdx.x * 128;
    if (causal && n0 > m0 + 127) return;      // fully-masked tile
    if (kcap && K > m0 + 128) K = m0 + 128;   // PV: probs zero beyond diagonal

    long long z = blockIdx.z;
    long long zo = z / zdiv, zi = z % zdiv;
    A  += zo * aO + zi * aI;
    Bm += zo * bO + zi * bI;
    size_t coff = (size_t)(zo * cO + zi * cI);
    const float* addb = addp ? addp + coff : nullptr;

    extern __shared__ __align__(16) char sm[];
    uint32_t sbase = smem_u32(sm);

    int tid = threadIdx.x, wid = tid >> 5, lane = tid & 31;
    int gid = lane >> 2, tig = lane & 3;
    int wm = (wid & 3) * 32, wn = (wid >> 2) * 64;

    // cp.async mapping: 2 threads per row; each covers 2 x 16B chunks
    int lrow = tid >> 1, lsel = tid & 1;
    const __half* aR = A + (size_t)(m0 + lrow) * lda + lsel * 16;
    const __half* bR = Bm + (size_t)(n0 + lrow) * ldb + lsel * 16;
    uint32_t dA = sbase + (uint32_t)(lrow * 80 + lsel * 32);
    uint32_t dB = dA + 10240u;

    int nch = K >> 5;
    auto issue = [&](int ch) {
        if (ch < nch) {
            uint32_t so = (uint32_t)(ch & 3) * STG_BYTES;
            int k0 = ch * 32;
            cp16(dA + so,      aR + k0);
            cp16(dA + so + 16, aR + k0 + 8);
            cp16(dB + so,      bR + k0);
            cp16(dB + so + 16, bR + k0 + 8);
        }
        CP_COMMIT();
    };

    // ldmatrix lane offsets
    int g8 = lane >> 3, l8 = lane & 7;
    uint32_t aoff = (uint32_t)((((g8 & 1) * 8 + l8) * 80) + (g8 >> 1) * 16);
    uint32_t boff = 10240u + (uint32_t)((((g8 >> 1) * 8 + l8) * 80) + (g8 & 1) * 16);

    float acc[2][8][4];
    #pragma unroll
    for (int i = 0; i < 2; i++)
        #pragma unroll
        for (int j = 0; j < 8; j++)
            #pragma unroll
            for (int r = 0; r < 4; r++) acc[i][j][r] = 0.f;

    issue(0); issue(1); issue(2);

    for (int ch = 0; ch < nch; ch++) {
        CP_WAIT(2);
        __syncthreads();
        issue(ch + 3);

        uint32_t stg = sbase + (uint32_t)(ch & 3) * STG_BYTES;
        uint32_t aw0 = stg + aoff + (uint32_t)(wm * 80);
        uint32_t aw1 = aw0 + 16u * 80u;
        uint32_t bw  = stg + boff + (uint32_t)(wn * 80);

        #pragma unroll
        for (int s = 0; s < 2; s++) {
            uint32_t a[2][4];
            ldsm4(a[0][0], a[0][1], a[0][2], a[0][3], aw0 + s * 32);
            ldsm4(a[1][0], a[1][1], a[1][2], a[1][3], aw1 + s * 32);
            uint32_t b[8][2];
            #pragma unroll
            for (int jj = 0; jj < 4; jj++) {
                uint32_t t0, t1, t2, t3;
                ldsm4(t0, t1, t2, t3, bw + (uint32_t)(jj * 16 * 80) + s * 32);
                b[2 * jj][0] = t0; b[2 * jj][1] = t1;
                b[2 * jj + 1][0] = t2; b[2 * jj + 1][1] = t3;
            }
            #pragma unroll
            for (int i = 0; i < 2; i++)
                #pragma unroll
                for (int j = 0; j < 8; j++)
                    mma_f16(acc[i][j], a[i], b[j]);
        }
    }

    // epilogue
    #pragma unroll
    for (int i = 0; i < 2; i++) {
        #pragma unroll
        for (int j = 0; j < 8; j++) {
            int r0 = m0 + wm + i * 16 + gid;
            int c  = n0 + wn + j * 8 + 2 * tig;
            #pragma unroll
            for (int hh = 0; hh < 2; hh++) {
                int r = r0 + hh * 8;
                float v0 = acc[i][j][2 * hh + 0] * alpha;
                float v1 = acc[i][j][2 * hh + 1] * alpha;
                if (bias) { v0 += bias[c]; v1 += bias[c + 1]; }
                if (doRelu) { v0 = fmaxf(v0, 0.f); v1 = fmaxf(v1, 0.f); }
                if (addb) {
                    const float* ap = addb + (size_t)r * ldc + c;
                    v0 += ap[0]; v1 += ap[1];
                }
                if (outHalf) {
                    __half2* cp = (__half2*)((__half*)Cv + coff + (size_t)r * ldc + c);
                    *cp = __floats2half2_rn(v0, v1);
                } else {
                    float2* cp = (float2*)((float*)Cv + coff + (size_t)r * ldc + c);
                    *cp = make_float2(v0, v1);
                }
            }
        }
    }
}

// ---------------------------------------------------------------------------
// Tiled transposes
// ---------------------------------------------------------------------------
__global__ void transpose_f2h(const float* __restrict__ in, __half* __restrict__ out,
                              int ldi, int ldo, int zdiv,
                              long long iO, long long iI, long long oO, long long oI) {
    __shared__ float tile[32][33];
    long long z = blockIdx.z;
    in  += (z / zdiv) * iO + (z % zdiv) * iI;
    out += (z / zdiv) * oO + (z % zdiv) * oI;
    int r0 = blockIdx.y * 32, c0 = blockIdx.x * 32;
    int tx = threadIdx.x & 31, ty = threadIdx.x >> 5;
    #pragma unroll
    for (int i = ty; i < 32; i += 8)
        tile[i][tx] = in[(size_t)(r0 + i) * ldi + c0 + tx];
    __syncthreads();
    #pragma unroll
    for (int i = ty; i < 32; i += 8)
        out[(size_t)(c0 + i) * ldo + r0 + tx] = __float2half_rn(tile[tx][i]);
}

__global__ void transpose_h2h(const __half* __restrict__ in, __half* __restrict__ out,
                              int ldi, int ldo, int zdiv,
                              long long iO, long long iI, long long oO, long long oI) {
    __shared__ __half tile[32][33];
    long long z = blockIdx.z;
    in  += (z / zdiv) * iO + (z % zdiv) * iI;
    out += (z / zdiv) * oO + (z % zdiv) * oI;
    int r0 = blockIdx.y * 32, c0 = blockIdx.x * 32;
    int tx = threadIdx.x & 31, ty = threadIdx.x >> 5;
    #pragma unroll
    for (int i = ty; i < 32; i += 8)
        tile[i][tx] = in[(size_t)(r0 + i) * ldi + c0 + tx];
    __syncthreads();
    #pragma unroll
    for (int i = ty; i < 32; i += 8)
        out[(size_t)(c0 + i) * ldo + r0 + tx] = tile[tx][i];
}

// ---------------------------------------------------------------------------
// Block reductions
// ---------------------------------------------------------------------------
__device__ __forceinline__ float blk_reduce_sum(float v) {
    __shared__ float sh[32];
    __syncthreads();
    int lane = threadIdx.x & 31, w = threadIdx.x >> 5;
    #pragma unroll
    for (int o = 16; o > 0; o >>= 1) v += __shfl_down_sync(0xffffffffu, v, o);
    if (lane == 0) sh[w] = v;
    __syncthreads();
    int nw = blockDim.x >> 5;
    if (w == 0) {
        v = (lane < nw) ? sh[lane] : 0.f;
        #pragma unroll
        for (int o = 16; o > 0; o >>= 1) v += __shfl_down_sync(0xffffffffu, v, o);
        if (lane == 0) sh[0] = v;
    }
    __syncthreads();
    return sh[0];
}
__device__ __forceinline__ float blk_reduce_max(float v) {
    __shared__ float sh[32];
    __syncthreads();
    int lane = threadIdx.x & 31, w = threadIdx.x >> 5;
    #pragma unroll
    for (int o = 16; o > 0; o >>= 1) v = fmaxf(v, __shfl_down_sync(0xffffffffu, v, o));
    if (lane == 0) sh[w] = v;
    __syncthreads();
    int nw = blockDim.x >> 5;
    if (w == 0) {
        v = (lane < nw) ? sh[lane] : -3.4e38f;
        #pragma unroll
        for (int o = 16; o > 0; o >>= 1) v = fmaxf(v, __shfl_down_sync(0xffffffffu, v, o));
        if (lane == 0) sh[0] = v;
    }
    __syncthreads();
    return sh[0];
}

// ---------------------------------------------------------------------------
// LayerNorm (fp32 stats, fp16 output -> feeds GEMMs)
// ---------------------------------------------------------------------------
__global__ void ln_kernel(const float* __restrict__ x, const float* __restrict__ g,
                          const float* __restrict__ b, __half* __restrict__ out) {
    size_t row = blockIdx.x;
    const float* xr = x + row * Cc;
    float s = 0.f, s2 = 0.f;
    for (int i = threadIdx.x; i < Cc; i += blockDim.x) {
        float v = xr[i]; s += v; s2 += v * v;
    }
    float S = blk_reduce_sum(s), S2 = blk_reduce_sum(s2);
    float mean = S * (1.0f / Cc);
    float var = S2 * (1.0f / Cc) - mean * mean;
    float inv = rsqrtf(var + EPSF);
    __half* orow = out + row * Cc;
    for (int i = threadIdx.x; i < Cc; i += blockDim.x)
        orow[i] = __float2half_rn((xr[i] - mean) * inv * g[i] + b[i]);
}

// ---------------------------------------------------------------------------
// BatchNorm over (B, C) per T-channel (full fp32: residual path)
// ---------------------------------------------------------------------------
__global__ void bn_kernel(const float* __restrict__ x, const float* __restrict__ g,
                          const float* __restrict__ bb, float* __restrict__ out) {
    int t = blockIdx.x;
    float s = 0.f, s2 = 0.f;
    for (int bi = 0; bi < Bb; bi++) {
        const float* xr = x + ((size_t)bi * Tt + t) * Cc;
        for (int c = threadIdx.x; c < Cc; c += blockDim.x) {
            float v = xr[c]; s += v; s2 += v * v;
        }
    }
    const float cnt = (float)(Bb * Cc);
    float S = blk_reduce_sum(s), S2 = blk_reduce_sum(s2);
    float mean = S / cnt;
    float var = S2 / cnt - mean * mean;
    float inv = rsqrtf(var + EPSF);
    float gg = g[t], bv = bb[t];
    for (int bi = 0; bi < Bb; bi++) {
        const float* xr = x + ((size_t)bi * Tt + t) * Cc;
        float* orow = out + ((size_t)bi * Tt + t) * Cc;
        for (int c = threadIdx.x; c < Cc; c += blockDim.x)
            orow[c] = (xr[c] - mean) * inv * gg + bv;
    }
}

// ---------------------------------------------------------------------------
// Causal row softmax on fp16 scores (fp32 math; exp recomputed to avoid
// double rounding; probs stored fp16)
// ---------------------------------------------------------------------------
__global__ void softmax_h(__half* __restrict__ s) {
    int t = blockIdx.x;
    size_t z = blockIdx.y;
    __half* row = s + (z * Tt + t) * (size_t)Tt;
    int n = t + 1;
    float mx = -3.4e38f;
    for (int i = threadIdx.x; i < n; i += blockDim.x)
        mx = fmaxf(mx, __half2float(row[i]));
    mx = blk_reduce_max(mx);
    float se = 0.f;
    for (int i = threadIdx.x; i < n; i += blockDim.x)
        se += expf(__half2float(row[i]) - mx);
    se = blk_reduce_sum(se);
    float inv = 1.0f / se;
    for (int i = threadIdx.x; i < n; i += blockDim.x)
        row[i] = __float2half_rn(expf(__half2float(row[i]) - mx) * inv);
    for (int i = n + threadIdx.x; i < Tt; i += blockDim.x)
        row[i] = __float2half_rn(0.f);
}

// ---------------------------------------------------------------------------
// Launch
// ---------------------------------------------------------------------------
extern "C" void kernel_launch(void* const* d_in, const int* in_sizes, int n_in,
                              void* d_out, int out_size) {
    const float* x     = (const float*)d_in[0];
    const float* wq    = (const float*)d_in[1];
    const float* wk    = (const float*)d_in[2];
    const float* wv    = (const float*)d_in[3];
    const float* wo    = (const float*)d_in[4];
    const float* bo    = (const float*)d_in[5];
    const float* ln1_g = (const float*)d_in[6];
    const float* ln1_b = (const float*)d_in[7];
    const float* ln2_g = (const float*)d_in[8];
    const float* ln2_b = (const float*)d_in[9];
    const float* w1    = (const float*)d_in[10];
    const float* b1    = (const float*)d_in[11];
    const float* w2    = (const float*)d_in[12];
    const float* b2    = (const float*)d_in[13];
    const float* bn1_g = (const float*)d_in[14];
    const float* bn1_b = (const float*)d_in[15];
    const float* bn2_g = (const float*)d_in[16];
    const float* bn2_b = (const float*)d_in[17];
    float* out = (float*)d_out;

    __half *h, *q, *k, *v, *s, *o, *f1, *wqT, *wkT, *wvT, *woT, *w1T, *w2T, *vt;
    float *x1, *x2, *f2;
    cudaGetSymbolAddress((void**)&h,  g_h);
    cudaGetSymbolAddress((void**)&q,  g_q);
    cudaGetSymbolAddress((void**)&k,  g_k);
    cudaGetSymbolAddress((void**)&v,  g_v);
    cudaGetSymbolAddress((void**)&s,  g_s);
    cudaGetSymbolAddress((void**)&o,  g_o);
    cudaGetSymbolAddress((void**)&f1, g_f1);
    cudaGetSymbolAddress((void**)&wqT, g_wqT);
    cudaGetSymbolAddress((void**)&wkT, g_wkT);
    cudaGetSymbolAddress((void**)&wvT, g_wvT);
    cudaGetSymbolAddress((void**)&woT, g_woT);
    cudaGetSymbolAddress((void**)&w1T, g_w1T);
    cudaGetSymbolAddress((void**)&w2T, g_w2T);
    cudaGetSymbolAddress((void**)&vt,  g_vt);
    cudaGetSymbolAddress((void**)&x1, g_x1);
    cudaGetSymbolAddress((void**)&x2, g_x2);
    cudaGetSymbolAddress((void**)&f2, g_f2);

    cudaFuncSetAttribute(hgemm, cudaFuncAttributeMaxDynamicSharedMemorySize, SMEM_BYTES);

    const long long CD = (long long)Cc * Dd;
    const long long TC = (long long)Tt * Cc;
    const long long TT = (long long)Tt * Tt;
    const long long DT = (long long)Dd * Tt;

    // --- weight transposes (N x K layout, fp16) ---
    transpose_f2h<<<dim3(Dd / 32, Cc / 32, Hh), 256>>>(wq, wqT, Dd, Cc, 1, CD, 0, CD, 0);
    transpose_f2h<<<dim3(Dd / 32, Cc / 32, Hh), 256>>>(wk, wkT, Dd, Cc, 1, CD, 0, CD, 0);
    transpose_f2h<<<dim3(Dd / 32, Cc / 32, Hh), 256>>>(wv, wvT, Dd, Cc, 1, CD, 0, CD, 0);
    transpose_f2h<<<dim3(Cc / 32, Cc / 32, 1), 256>>>(wo, woT, Cc, Cc, 1, 0, 0, 0, 0);
    transpose_f2h<<<dim3(Ff / 32, Cc / 32, 1), 256>>>(w1, w1T, Ff, Cc, 1, 0, 0, 0, 0);
    transpose_f2h<<<dim3(Cc / 32, Ff / 32, 1), 256>>>(w2, w2T, Cc, Ff, 1, 0, 0, 0, 0);

    // 1. LN1 -> h (fp16)
    ln_kernel<<<BT, 256>>>(x, ln1_g, ln1_b, h);

    // 2. QKV: per-head NT GEMM, M=8192, N=128, K=1536 -> fp16
    {
        dim3 g(1, BT / 128, Hh);
        hgemm<<<g, 256, SMEM_BYTES>>>(h, wqT, q, BT, Dd, Cc, Cc, Cc, Cc, 1.f,
                                      nullptr, nullptr, 0, 1, 0, 0, 1 << 30,
                                      0, 0, 0, CD, 0, (long long)Dd);
        hgemm<<<g, 256, SMEM_BYTES>>>(h, wkT, k, BT, Dd, Cc, Cc, Cc, Cc, 1.f,
                                      nullptr, nullptr, 0, 1, 0, 0, 1 << 30,
                                      0, 0, 0, CD, 0, (long long)Dd);
        hgemm<<<g, 256, SMEM_BYTES>>>(h, wvT, v, BT, Dd, Cc, Cc, Cc, Cc, 1.f,
                                      nullptr, nullptr, 0, 1, 0, 0, 1 << 30,
                                      0, 0, 0, CD, 0, (long long)Dd);
    }

    // v -> vT (per b,h: [T,D] -> [D,T])
    transpose_h2h<<<dim3(Dd / 32, Tt / 32, Bb * Hh), 256>>>(
        v, vt, Cc, Tt, Hh, TC, (long long)Dd, (long long)Hh * DT, DT);

    // 3. scores = alpha * Q K^T — causal tile skip -> fp16
    {
        dim3 g(Tt / 128, Tt / 128, Bb * Hh);
        hgemm<<<g, 256, SMEM_BYTES>>>(q, k, s, Tt, Tt, Dd, Cc, Cc, Tt,
                                      0.08838834764831843f,
                                      nullptr, nullptr, 0, 1, 1, 0, Hh,
                                      TC, (long long)Dd, TC, (long long)Dd,
                                      (long long)Hh * TT, TT);
    }

    // 4. causal softmax (fp16 probs)
    softmax_h<<<dim3(Tt, Bb * Hh), 128>>>(s);

    // 5. O = P V (K capped at diagonal) -> fp16
    {
        dim3 g(1, Tt / 128, Bb * Hh);
        hgemm<<<g, 256, SMEM_BYTES>>>(s, vt, o, Tt, Dd, Tt, Tt, Tt, Cc, 1.f,
                                      nullptr, nullptr, 0, 1, 0, 1, Hh,
                                      (long long)Hh * TT, TT, (long long)Hh * DT, DT,
                                      TC, (long long)Dd);
    }

    // 6. x1 = x + (O @ wo + bo)  (fp32 out)
    {
        dim3 g(Cc / 128, BT / 128, 1);
        hgemm<<<g, 256, SMEM_BYTES>>>(o, woT, x1, BT, Cc, Cc, Cc, Cc, Cc, 1.f,
                                      bo, x, 0, 0, 0, 0, 1, 0, 0, 0, 0, 0, 0);
    }

    // 7. bn1
    bn_kernel<<<Tt, 256>>>(x1, bn1_g, bn1_b, x2);

    // 8. LN2 -> h (fp16)
    ln_kernel<<<BT, 256>>>(x2, ln2_g, ln2_b, h);

    // 9. f1 = relu(h @ w1 + b1) -> fp16
    {
        dim3 g(Ff / 128, BT / 128, 1);
        hgemm<<<g, 256, SMEM_BYTES>>>(h, w1T, f1, BT, Ff, Cc, Cc, Cc, Ff, 1.f,
                                      b1, nullptr, 1, 1, 0, 0, 1, 0, 0, 0, 0, 0, 0);
    }

    // 10. f2 = x2 + (f1 @ w2 + b2)  (fp32 out)
    {
        dim3 g(Cc / 128, BT / 128, 1);
        hgemm<<<g, 256, SMEM_BYTES>>>(f1, w2T, f2, BT, Cc, Ff, Ff, Ff, Cc, 1.f,
                                      b2, x2, 0, 0, 0, 0, 1, 0, 0, 0, 0, 0, 0);
    }

    // 11. bn2 -> out
    bn_kernel<<<Tt, 256>>>(f2, bn2_g, bn2_b, out);
}